// round 2
// baseline (speedup 1.0000x reference)
#include <cuda_runtime.h>
#include <math.h>
#include <float.h>

#define NB 16
#define NA 5
#define NH 96
#define NW 96
#define MAXT 50
#define NCLS 40
#define CH (5 + NCLS)          // 45
#define NCELL (NB*NA*NH*NW)    // 737280
#define PLANE (NH*NW)          // 9216
#define MAXE 304               // max correction entries per batch (50 best + 250 ignore)

#define CORR_BLOCKS 8
#define SWEEP_THREADS 256
#define CELLS_PER_THREAD 4
#define SWEEP_BLOCKS (NCELL / (SWEEP_THREADS * CELLS_PER_THREAD))   // 720 exact
#define TOTAL_BLOCKS (CORR_BLOCKS + SWEEP_BLOCKS)

// Compact correction list (no big maps, no init kernel)
__device__ int   g_ecnt[NB];
__device__ int   g_ecell[NB * MAXE];
__device__ int   g_einfo[NB * MAXE];   // bit0: m, bit1: cm, bits2+: label
__device__ float g_etx[NB * MAXE];
__device__ float g_ety[NB * MAXE];
__device__ float g_etw[NB * MAXE];
__device__ float g_eth[NB * MAXE];
__device__ float g_nGT[NB];
__device__ float g_nC[NB];
// acc: 0 sx,1 sy,2 sw,3 sh,4 neg_sum,5 neg_cnt_delta,6 pos_sum,7 nM,8 cls_sum,9 nProp
__device__ float g_acc[12];
__device__ int   g_done;

__global__ void k_build(const float* __restrict__ pred,
                        const float* __restrict__ target,
                        const int*   __restrict__ tsizes) {
    const int b = blockIdx.x;
    const int t = threadIdx.x;

    __shared__ int      s_gi[MAXT], s_gj[MAXT], s_best[MAXT], s_cor[MAXT];
    __shared__ unsigned s_ign[MAXT];
    __shared__ int      s_cnt;

    if (t == 0) s_cnt = 0;
    // Zero global accumulators for this replay (block 0 is sole writer; K2 runs after)
    if (b == 0) {
        if (t < 12) g_acc[t] = 0.0f;
        if (t == 12) g_done = 0;
    }

    int ts = tsizes[b];
    if (ts > MAXT) ts = MAXT;

    const float AW[5] = {1.f, 2.f, 4.f, 2.f, 4.f};
    const float AH[5] = {1.f, 2.f, 4.f, 4.f, 2.f};

    float l_tx = 0.f, l_ty = 0.f, l_tw = 0.f, l_th = 0.f;
    int   l_lbl = 0;

    if (t < ts) {
        const float* row = target + ((long)(b * MAXT + t)) * (13 + NCLS);
        float gx = row[0] * (1.0f / 16.0f);
        float gy = row[1] * (1.0f / 16.0f);
        float gh = row[3] * (1.0f / 16.0f);
        float gw = row[4] * (1.0f / 16.0f);
        int gi = (int)gx;
        int gj = (int)gy;

        // label = argmax over one-hot (first max)
        int lbl = 0; float bv = row[13];
        #pragma unroll
        for (int c = 1; c < NCLS; c++) {
            float v = row[13 + c];
            if (v > bv) { bv = v; lbl = c; }
        }
        l_lbl = lbl;

        // anchor IoUs
        float garea = (gw + 1.0f) * (gh + 1.0f);
        float best_iou = -1.0f; int best = 0; unsigned ign = 0u;
        #pragma unroll
        for (int a = 0; a < 5; a++) {
            float iw = fmaxf(fminf(gw, AW[a]) + 1.0f, 0.0f);
            float ih = fmaxf(fminf(gh, AH[a]) + 1.0f, 0.0f);
            float inter = iw * ih;
            float aa = (AW[a] + 1.0f) * (AH[a] + 1.0f);
            float iou = inter / (garea + aa - inter + 1e-16f);
            if (iou > 0.5f) ign |= (1u << a);
            if (iou > best_iou) { best_iou = iou; best = a; }  // first-max tie rule
        }

        s_gi[t] = gi; s_gj[t] = gj; s_best[t] = best; s_ign[t] = ign;
        l_tx = gx - (float)gi;
        l_ty = gy - (float)gj;
        l_tw = logf(gw / AW[best] + 1e-16f);
        l_th = logf(gh / AH[best] + 1e-16f);

        // prediction at best cell (for nCorrect)
        long base = ((((long)b * NA + best) * NH + gj) * NW + gi) * CH;
        float pc = pred[base + 0];
        float x = pred[base + 1], y = pred[base + 2];
        float h = pred[base + 3], w = pred[base + 4];
        float px = x + (float)gi, py = y + (float)gj;
        float pw = expf(w) * AW[best];
        float ph = expf(h) * AH[best];

        float gx1 = gx - gw * 0.5f, gx2 = gx + gw * 0.5f;
        float gy1 = gy - gh * 0.5f, gy2 = gy + gh * 0.5f;
        float px1 = px - pw * 0.5f, px2 = px + pw * 0.5f;
        float py1 = py - ph * 0.5f, py2 = py + ph * 0.5f;
        float iw2 = fmaxf(fminf(gx2, px2) - fmaxf(gx1, px1) + 1.0f, 0.0f);
        float ih2 = fmaxf(fminf(gy2, py2) - fmaxf(gy1, py1) + 1.0f, 0.0f);
        float inter2 = iw2 * ih2;
        float ga = (gx2 - gx1 + 1.0f) * (gy2 - gy1 + 1.0f);
        float pa = (px2 - px1 + 1.0f) * (py2 - py1 + 1.0f);
        float iou2 = inter2 / (ga + pa - inter2 + 1e-16f);

        int cb = 0; float cbv = pred[base + 5];
        #pragma unroll
        for (int c = 1; c < NCLS; c++) {
            float v = pred[base + 5 + c];
            if (v > cbv) { cbv = v; cb = c; }
        }
        s_cor[t] = (iou2 > 0.5f && cb == lbl && pc > 0.5f) ? 1 : 0;
    }
    __syncthreads();

    // Last-writer-wins analysis (parallel over targets); emit compact corrections.
    if (t < ts) {
        const int gi = s_gi[t], gj = s_gj[t], best = s_best[t];

        // Owner = last target whose best event hits this cell
        bool owner = true;
        for (int u = t + 1; u < ts; u++)
            if (s_best[u] == best && s_gj[u] == gj && s_gi[u] == gi) { owner = false; break; }
        if (owner) {
            // Last ignorer of this cell (scan all targets; later index wins)
            int Lign = -1;
            for (int u = 0; u < ts; u++)
                if (s_gj[u] == gj && s_gi[u] == gi && ((s_ign[u] >> best) & 1u)) Lign = u;
            int cm = (Lign > t) ? 0 : 1;   // within same target, best write lands after ignore
            int idx = atomicAdd(&s_cnt, 1);
            int gidx = b * MAXE + idx;
            g_ecell[gidx] = b * (NA * PLANE) + best * PLANE + gj * NW + gi;
            g_einfo[gidx] = 1 | (cm << 1) | (l_lbl << 2);
            g_etx[gidx] = l_tx; g_ety[gidx] = l_ty;
            g_etw[gidx] = l_tw; g_eth[gidx] = l_th;
        }

        // Pure-ignore cells (no best event ever): final (m=0, cm=0)
        #pragma unroll
        for (int a = 0; a < 5; a++) {
            if (!((s_ign[t] >> a) & 1u)) continue;
            bool claim = true;   // claim iff t is the last ignorer of (a,gj,gi)
            for (int u = t + 1; u < ts; u++)
                if (s_gj[u] == gj && s_gi[u] == gi && ((s_ign[u] >> a) & 1u)) { claim = false; break; }
            if (!claim) continue;
            bool hasbest = false;
            for (int u = 0; u < ts; u++)
                if (s_best[u] == a && s_gj[u] == gj && s_gi[u] == gi) { hasbest = true; break; }
            if (hasbest) continue;  // handled by that cell's owner entry
            int idx = atomicAdd(&s_cnt, 1);
            int gidx = b * MAXE + idx;
            g_ecell[gidx] = b * (NA * PLANE) + a * PLANE + gj * NW + gi;
            g_einfo[gidx] = 0;
        }
    }
    __syncthreads();

    if (t == 0) {
        g_ecnt[b] = s_cnt;
        int nC = 0;
        for (int i = 0; i < ts; i++) nC += s_cor[i];
        g_nGT[b] = (float)ts;
        g_nC[b]  = (float)nC;
    }
}

__global__ void k_sweep(const float* __restrict__ pred, float* __restrict__ out) {
    float acc[10];
    #pragma unroll
    for (int k = 0; k < 10; k++) acc[k] = 0.0f;

    if (blockIdx.x < CORR_BLOCKS) {
        // ---- correction path: apply exact deltas vs. default (m=0, cm=1) ----
        const int tid = blockIdx.x * blockDim.x + threadIdx.x;
        const int stride = CORR_BLOCKS * blockDim.x;
        for (int b = 0; b < NB; b++) {
            int cnt = g_ecnt[b];
            for (int i = tid; i < cnt; i += stride) {
                int gidx = b * MAXE + i;
                int cell = g_ecell[gidx];
                int info = g_einfo[gidx];
                const float* p = pred + (long)cell * CH;
                float pc = p[0];
                float bce0 = fmaxf(pc, 0.0f) + log1pf(expf(-fabsf(pc)));
                if (info & 1) {             // masked cell
                    float bce1 = bce0 - pc;
                    if ((info >> 1) & 1) {  // cm=1: cmf 1 -> 0
                        acc[4] -= bce0; acc[5] -= 1.0f;
                    } else {                // cm=0,m=1: cmf stays 1 but bce uses m=1
                        acc[4] += bce1 - bce0;
                    }
                    acc[6] += bce1;         // pos bce
                    acc[7] += 1.0f;         // nM
                    float dx = p[1] - g_etx[gidx]; acc[0] += dx * dx;
                    float dy = p[2] - g_ety[gidx]; acc[1] += dy * dy;
                    float dw = p[4] - g_etw[gidx]; acc[2] += dw * dw;
                    float dh = p[3] - g_eth[gidx]; acc[3] += dh * dh;
                    int lbl = info >> 2;
                    float mx = -FLT_MAX;
                    for (int c = 0; c < NCLS; c++) mx = fmaxf(mx, p[5 + c]);
                    float s = 0.0f;
                    for (int c = 0; c < NCLS; c++) s += expf(p[5 + c] - mx);
                    acc[8] += -(p[5 + lbl] - mx - logf(s));
                } else {                    // pure-ignore cell: (0,0) -> cmf 1 -> 0
                    acc[4] -= bce0; acc[5] -= 1.0f;
                }
            }
        }
    } else {
        // ---- default sweep: only conf channel needed ----
        const int base = (blockIdx.x - CORR_BLOCKS) * (SWEEP_THREADS * CELLS_PER_THREAD) + threadIdx.x;
        #pragma unroll
        for (int k = 0; k < CELLS_PER_THREAD; k++) {
            int cell = base + k * SWEEP_THREADS;
            float pc = __ldg(pred + (long)cell * CH);
            acc[4] += fmaxf(pc, 0.0f) + log1pf(expf(-fabsf(pc)));
            acc[9] += (pc > 0.0f) ? 1.0f : 0.0f;
        }
    }

    // ---- block reduction of 10 accumulators ----
    __shared__ float red[SWEEP_THREADS / 32][10];
    const int lane = threadIdx.x & 31;
    const int warp = threadIdx.x >> 5;
    #pragma unroll
    for (int k = 0; k < 10; k++) {
        float x = acc[k];
        #pragma unroll
        for (int off = 16; off > 0; off >>= 1)
            x += __shfl_down_sync(0xFFFFFFFFu, x, off);
        if (lane == 0) red[warp][k] = x;
    }
    __syncthreads();
    if (threadIdx.x == 0) {
        #pragma unroll
        for (int k = 0; k < 10; k++) {
            float x = 0.0f;
            for (int w = 0; w < SWEEP_THREADS / 32; w++) x += red[w][k];
            if (x != 0.0f) atomicAdd(&g_acc[k], x);
        }
        __threadfence();
        int old = atomicAdd(&g_done, 1);
        if (old == TOTAL_BLOCKS - 1) {
            // all blocks' g_acc updates are visible (each fenced before its counter add)
            volatile float* A = g_acc;
            float nM = A[7];
            float lx = A[0] / nM, ly = A[1] / nM, lw = A[2] / nM, lh = A[3] / nM;
            float neg_cnt = (float)NCELL + A[5];
            float lconf = A[4] / neg_cnt + A[6] / nM;
            float lcls = (1.0f / (float)NB) * A[8] / nM;
            float nGT = 0.0f, nC = 0.0f;
            for (int b = 0; b < NB; b++) { nGT += g_nGT[b]; nC += g_nC[b]; }
            float nP = A[9];
            out[0] = lx + ly + lw + lh + lconf + lcls;
            out[1] = lx + ly + lw + lh;
            out[2] = lconf;
            out[3] = lcls;
            out[4] = nC / fmaxf(nGT, 1.0f);
            out[5] = (nP > 0.0f) ? (nC / fmaxf(nP, 1.0f)) : 1.0f;
        }
    }
}

extern "C" void kernel_launch(void* const* d_in, const int* in_sizes, int n_in,
                              void* d_out, int out_size) {
    const float* pred   = (const float*)d_in[0];
    const float* target = (const float*)d_in[1];
    const int*   tsz    = (const int*)d_in[2];
    float* out = (float*)d_out;
    (void)in_sizes; (void)n_in; (void)out_size;

    k_build<<<NB, 64>>>(pred, target, tsz);
    k_sweep<<<TOTAL_BLOCKS, SWEEP_THREADS>>>(pred, out);
}

// round 3
// speedup vs baseline: 2.1290x; 2.1290x over previous
#include <cuda_runtime.h>
#include <math.h>
#include <float.h>

#define NB 16
#define NA 5
#define NH 96
#define NW 96
#define MAXT 50
#define NCLS 40
#define CH (5 + NCLS)          // 45
#define NCELL (NB*NA*NH*NW)    // 737280
#define PLANE (NH*NW)          // 9216
#define MAXE 304               // max correction entries per batch

#define CORR_BLOCKS 8
#define SWEEP_THREADS 256
#define CELLS_PER_THREAD 2
#define SWEEP_BLOCKS (NCELL / (SWEEP_THREADS * CELLS_PER_THREAD))   // 1440 exact
#define TOTAL_BLOCKS (CORR_BLOCKS + SWEEP_BLOCKS)

// Compact correction list (no big maps, no init kernel)
__device__ int   g_ecnt[NB];
__device__ int   g_ecell[NB * MAXE];
__device__ int   g_einfo[NB * MAXE];   // bit0: m, bit1: cm, bits2+: label
__device__ float g_etx[NB * MAXE];
__device__ float g_ety[NB * MAXE];
__device__ float g_etw[NB * MAXE];
__device__ float g_eth[NB * MAXE];
__device__ float g_nGT[NB];
__device__ float g_nC[NB];
// acc: 0 sx,1 sy,2 sw,3 sh,4 neg_sum,5 neg_cnt_delta,6 pos_sum,7 nM,8 cls_sum,9 nProp
__device__ float g_acc[12];
__device__ int   g_done;

__global__ void __launch_bounds__(64) k_build(const float* __restrict__ pred,
                                              const float* __restrict__ target,
                                              const int*   __restrict__ tsizes) {
    const int b = blockIdx.x;
    const int t = threadIdx.x;

    __shared__ int   pos_map[PLANE];            // 36 KB: grid-pos -> claiming target (min t)
    __shared__ int   lastBest[MAXT * NA];       // last target whose best-event hit (slot,a)
    __shared__ int   lastIgn[MAXT * NA];        // last target whose ignore-event hit (slot,a)
    __shared__ int   s_gi[MAXT], s_gj[MAXT], s_lbl[MAXT], s_cor[MAXT];
    __shared__ float s_tx[MAXT], s_ty[MAXT], s_tw[MAXT], s_th[MAXT];
    __shared__ int   s_cnt;

    if (t == 0) s_cnt = 0;
    if (b == 0) {
        if (t < 12) g_acc[t] = 0.0f;
        if (t == 12) g_done = 0;
    }
    // init shared maps
    for (int i = t; i < PLANE; i += 64) pos_map[i] = 0x7FFFFFFF;
    for (int i = t; i < MAXT * NA; i += 64) { lastBest[i] = -1; lastIgn[i] = -1; }
    __syncthreads();

    int ts = tsizes[b];
    if (ts > MAXT) ts = MAXT;

    const float AW[5] = {1.f, 2.f, 4.f, 2.f, 4.f};
    const float AH[5] = {1.f, 2.f, 4.f, 4.f, 2.f};

    if (t < ts) {
        const float* row = target + ((long)(b * MAXT + t)) * (13 + NCLS);
        float gx = row[0] * (1.0f / 16.0f);
        float gy = row[1] * (1.0f / 16.0f);
        float gh = row[3] * (1.0f / 16.0f);
        float gw = row[4] * (1.0f / 16.0f);
        int gi = (int)gx;
        int gj = (int)gy;
        int pos = gj * NW + gi;

        // claim position (deterministic: min target index owns the slot id)
        atomicMin(&pos_map[pos], t);

        // label = argmax over one-hot (first max)
        int lbl = 0; float bv = row[13];
        #pragma unroll
        for (int c = 1; c < NCLS; c++) {
            float v = row[13 + c];
            if (v > bv) { bv = v; lbl = c; }
        }

        // anchor IoUs
        float garea = (gw + 1.0f) * (gh + 1.0f);
        float best_iou = -1.0f; int best = 0; unsigned ign = 0u;
        #pragma unroll
        for (int a = 0; a < 5; a++) {
            float iw = fmaxf(fminf(gw, AW[a]) + 1.0f, 0.0f);
            float ih = fmaxf(fminf(gh, AH[a]) + 1.0f, 0.0f);
            float inter = iw * ih;
            float aa = (AW[a] + 1.0f) * (AH[a] + 1.0f);
            float iou = inter / (garea + aa - inter + 1e-16f);
            if (iou > 0.5f) ign |= (1u << a);
            if (iou > best_iou) { best_iou = iou; best = a; }  // first-max tie rule
        }

        s_gi[t] = gi; s_gj[t] = gj; s_lbl[t] = lbl;
        s_tx[t] = gx - (float)gi;
        s_ty[t] = gy - (float)gj;
        s_tw[t] = logf(gw / AW[best] + 1e-16f);
        s_th[t] = logf(gh / AH[best] + 1e-16f);

        // defer LWW events until slot owners are resolved (need pos_map settled)
        __syncwarp(__activemask());
        // (claims done above; slot id read happens after block sync below — but we
        //  can record events now using pos, resolving slot afterwards is wrong;
        //  instead record events directly after a sync. Store pos+best+ign for phase 2.)
        s_cor[t] = (int)ign | (best << 8) | (pos << 16);   // temp pack (pos<16384 fits)

        // prediction at best cell (for nCorrect) — independent of overwrites
        long base = ((((long)b * NA + best) * NH + gj) * NW + gi) * CH;
        float pc = pred[base + 0];
        float x = pred[base + 1], y = pred[base + 2];
        float h = pred[base + 3], w = pred[base + 4];
        float px = x + (float)gi, py = y + (float)gj;
        float pw = expf(w) * AW[best];
        float ph = expf(h) * AH[best];

        float gx1 = gx - gw * 0.5f, gx2 = gx + gw * 0.5f;
        float gy1 = gy - gh * 0.5f, gy2 = gy + gh * 0.5f;
        float px1 = px - pw * 0.5f, px2 = px + pw * 0.5f;
        float py1 = py - ph * 0.5f, py2 = py + ph * 0.5f;
        float iw2 = fmaxf(fminf(gx2, px2) - fmaxf(gx1, px1) + 1.0f, 0.0f);
        float ih2 = fmaxf(fminf(gy2, py2) - fmaxf(gy1, py1) + 1.0f, 0.0f);
        float inter2 = iw2 * ih2;
        float ga = (gx2 - gx1 + 1.0f) * (gy2 - gy1 + 1.0f);
        float pa = (px2 - px1 + 1.0f) * (py2 - py1 + 1.0f);
        float iou2 = inter2 / (ga + pa - inter2 + 1e-16f);

        int cb = 0; float cbv = pred[base + 5];
        #pragma unroll
        for (int c = 1; c < NCLS; c++) {
            float v = pred[base + 5 + c];
            if (v > cbv) { cbv = v; cb = c; }
        }
        int correct = (iou2 > 0.5f && cb == lbl && pc > 0.5f) ? 1 : 0;
        s_cor[t] |= (correct << 30);
    }
    __syncthreads();

    // Phase 2: record LWW events against resolved slots
    if (t < ts) {
        int pk   = s_cor[t];
        int pos  = (pk >> 16) & 0x3FFF;
        int best = (pk >> 8) & 0xFF;
        unsigned ign = (unsigned)(pk & 0xFF);
        int slot = pos_map[pos];               // claiming target index (0..ts-1)
        atomicMax(&lastBest[slot * NA + best], t);
        #pragma unroll
        for (int a = 0; a < 5; a++)
            if ((ign >> a) & 1u) atomicMax(&lastIgn[slot * NA + a], t);
    }
    __syncthreads();

    // Phase 3: emit corrections (slot owners only); final state per (slot, anchor):
    //   m = (lastBest >= 0); owner = lastBest; cm = (lastBest >= lastIgn)
    if (t < ts) {
        int pos = s_gj[t] * NW + s_gi[t];
        if (pos_map[pos] == t) {   // I own this slot
            #pragma unroll
            for (int a = 0; a < 5; a++) {
                int lb = lastBest[t * NA + a];
                int li = lastIgn[t * NA + a];
                if (lb >= 0) {
                    int cm = (lb >= li) ? 1 : 0;
                    int idx = atomicAdd(&s_cnt, 1);
                    int gidx = b * MAXE + idx;
                    g_ecell[gidx] = b * (NA * PLANE) + a * PLANE + pos;
                    g_einfo[gidx] = 1 | (cm << 1) | (s_lbl[lb] << 2);
                    g_etx[gidx] = s_tx[lb]; g_ety[gidx] = s_ty[lb];
                    g_etw[gidx] = s_tw[lb]; g_eth[gidx] = s_th[lb];
                } else if (li >= 0) {   // pure-ignore cell: (m=0, cm=0)
                    int idx = atomicAdd(&s_cnt, 1);
                    int gidx = b * MAXE + idx;
                    g_ecell[gidx] = b * (NA * PLANE) + a * PLANE + pos;
                    g_einfo[gidx] = 0;
                }
            }
        }
    }
    __syncthreads();

    if (t == 0) {
        g_ecnt[b] = s_cnt;
        int nC = 0;
        for (int i = 0; i < ts; i++) nC += (s_cor[i] >> 30) & 1;
        g_nGT[b] = (float)ts;
        g_nC[b]  = (float)nC;
    }
}

__global__ void __launch_bounds__(SWEEP_THREADS) k_sweep(const float* __restrict__ pred,
                                                         float* __restrict__ out) {
    __shared__ float red[SWEEP_THREADS / 32][10];
    const int lane = threadIdx.x & 31;
    const int warp = threadIdx.x >> 5;

    if (blockIdx.x >= CORR_BLOCKS) {
        // ---- default sweep: only conf channel; 2 accumulators ----
        const int base = (blockIdx.x - CORR_BLOCKS) * (SWEEP_THREADS * CELLS_PER_THREAD) + threadIdx.x;
        float p0 = __ldg(pred + (size_t)base * CH);
        float p1 = __ldg(pred + (size_t)(base + SWEEP_THREADS) * CH);
        float neg = fmaxf(p0, 0.0f) + log1pf(expf(-fabsf(p0)))
                  + fmaxf(p1, 0.0f) + log1pf(expf(-fabsf(p1)));
        float np  = ((p0 > 0.0f) ? 1.0f : 0.0f) + ((p1 > 0.0f) ? 1.0f : 0.0f);
        #pragma unroll
        for (int off = 16; off > 0; off >>= 1) {
            neg += __shfl_down_sync(0xFFFFFFFFu, neg, off);
            np  += __shfl_down_sync(0xFFFFFFFFu, np, off);
        }
        if (lane == 0) { red[warp][0] = neg; red[warp][1] = np; }
        __syncthreads();
        if (threadIdx.x == 0) {
            float sn = 0.0f, sp = 0.0f;
            #pragma unroll
            for (int w = 0; w < SWEEP_THREADS / 32; w++) { sn += red[w][0]; sp += red[w][1]; }
            atomicAdd(&g_acc[4], sn);
            atomicAdd(&g_acc[9], sp);
        }
    } else {
        // ---- correction path: exact deltas vs default (m=0, cm=1) ----
        float acc[10];
        #pragma unroll
        for (int k = 0; k < 10; k++) acc[k] = 0.0f;

        const int tid = blockIdx.x * SWEEP_THREADS + threadIdx.x;
        const int stride = CORR_BLOCKS * SWEEP_THREADS;
        for (int b = 0; b < NB; b++) {
            int cnt = g_ecnt[b];
            for (int i = tid; i < cnt; i += stride) {
                int gidx = b * MAXE + i;
                int cell = g_ecell[gidx];
                int info = g_einfo[gidx];
                const float* p = pred + (size_t)cell * CH;
                float pc = p[0];
                float bce0 = fmaxf(pc, 0.0f) + log1pf(expf(-fabsf(pc)));
                if (info & 1) {             // masked cell
                    float bce1 = bce0 - pc;
                    if ((info >> 1) & 1) {  // cm=1: cmf 1 -> 0
                        acc[4] -= bce0; acc[5] -= 1.0f;
                    } else {                // cm=0,m=1: cmf stays 1, bce uses tconf=1
                        acc[4] += bce1 - bce0;
                    }
                    acc[6] += bce1;
                    acc[7] += 1.0f;
                    float dx = p[1] - g_etx[gidx]; acc[0] += dx * dx;
                    float dy = p[2] - g_ety[gidx]; acc[1] += dy * dy;
                    float dw = p[4] - g_etw[gidx]; acc[2] += dw * dw;
                    float dh = p[3] - g_eth[gidx]; acc[3] += dh * dh;
                    int lbl = info >> 2;
                    float mx = -FLT_MAX;
                    for (int c = 0; c < NCLS; c++) mx = fmaxf(mx, p[5 + c]);
                    float s = 0.0f;
                    for (int c = 0; c < NCLS; c++) s += expf(p[5 + c] - mx);
                    acc[8] += -(p[5 + lbl] - mx - logf(s));
                } else {                    // pure-ignore: cmf 1 -> 0
                    acc[4] -= bce0; acc[5] -= 1.0f;
                }
            }
        }

        #pragma unroll
        for (int k = 0; k < 10; k++) {
            float x = acc[k];
            #pragma unroll
            for (int off = 16; off > 0; off >>= 1)
                x += __shfl_down_sync(0xFFFFFFFFu, x, off);
            if (lane == 0) red[warp][k] = x;
        }
        __syncthreads();
        if (threadIdx.x == 0) {
            #pragma unroll
            for (int k = 0; k < 10; k++) {
                float x = 0.0f;
                #pragma unroll
                for (int w = 0; w < SWEEP_THREADS / 32; w++) x += red[w][k];
                if (x != 0.0f) atomicAdd(&g_acc[k], x);
            }
        }
    }

    // ---- last-block-done finalization ----
    if (threadIdx.x == 0) {
        __threadfence();
        int old = atomicAdd(&g_done, 1);
        if (old == TOTAL_BLOCKS - 1) {
            volatile float* A = g_acc;
            float nM = A[7];
            float lx = A[0] / nM, ly = A[1] / nM, lw = A[2] / nM, lh = A[3] / nM;
            float neg_cnt = (float)NCELL + A[5];
            float lconf = A[4] / neg_cnt + A[6] / nM;
            float lcls = (1.0f / (float)NB) * A[8] / nM;
            float nGT = 0.0f, nC = 0.0f;
            for (int b = 0; b < NB; b++) { nGT += g_nGT[b]; nC += g_nC[b]; }
            float nP = A[9];
            out[0] = lx + ly + lw + lh + lconf + lcls;
            out[1] = lx + ly + lw + lh;
            out[2] = lconf;
            out[3] = lcls;
            out[4] = nC / fmaxf(nGT, 1.0f);
            out[5] = (nP > 0.0f) ? (nC / fmaxf(nP, 1.0f)) : 1.0f;
        }
    }
}

extern "C" void kernel_launch(void* const* d_in, const int* in_sizes, int n_in,
                              void* d_out, int out_size) {
    const float* pred   = (const float*)d_in[0];
    const float* target = (const float*)d_in[1];
    const int*   tsz    = (const int*)d_in[2];
    float* out = (float*)d_out;
    (void)in_sizes; (void)n_in; (void)out_size;

    k_build<<<NB, 64>>>(pred, target, tsz);
    k_sweep<<<TOTAL_BLOCKS, SWEEP_THREADS>>>(pred, out);
}

// round 4
// speedup vs baseline: 2.3552x; 1.1062x over previous
#include <cuda_runtime.h>
#include <math.h>
#include <float.h>

#define NB 16
#define NA 5
#define NH 96
#define NW 96
#define MAXT 50
#define NCLS 40
#define CH (5 + NCLS)          // 45
#define NCELL (NB*NA*NH*NW)    // 737280
#define NFLOAT (NCELL*CH)      // 33,177,600 floats
#define NF4 (NFLOAT/4)         // 8,294,400 float4
#define PLANE (NH*NW)          // 9216
#define MAXE 304

#define CORR_BLOCKS 8
#define MAIN_THREADS 256
#define F4_PER_THREAD 20
#define STREAM_BLOCKS (NF4 / (MAIN_THREADS * F4_PER_THREAD))   // 1620 exact
#define TOTAL_BLOCKS (CORR_BLOCKS + STREAM_BLOCKS)

// Compact correction list
__device__ int   g_ecnt[NB];
__device__ int   g_ecell[NB * MAXE];
__device__ int   g_einfo[NB * MAXE];   // bit0: m, bit1: cm, bits2+: label
__device__ float g_etx[NB * MAXE];
__device__ float g_ety[NB * MAXE];
__device__ float g_etw[NB * MAXE];
__device__ float g_eth[NB * MAXE];
__device__ float g_nGT[NB];
__device__ float g_nC[NB];
// acc: 0 sx,1 sy,2 sw,3 sh,4 neg_sum,5 neg_cnt_delta,6 pos_sum,7 nM,8 cls_sum,9 nProp
__device__ float g_acc[12];
__device__ int   g_done;

__global__ void __launch_bounds__(64) k_build(const float* __restrict__ pred,
                                              const float* __restrict__ target,
                                              const int*   __restrict__ tsizes) {
    const int b = blockIdx.x;
    const int t = threadIdx.x;

    __shared__ int   pos_map[PLANE];            // grid-pos -> claiming target (min t)
    __shared__ int   lastBest[MAXT * NA];
    __shared__ int   lastIgn[MAXT * NA];
    __shared__ int   s_gi[MAXT], s_gj[MAXT], s_lbl[MAXT], s_cor[MAXT];
    __shared__ float s_tx[MAXT], s_ty[MAXT], s_tw[MAXT], s_th[MAXT];
    __shared__ int   s_cnt;

    if (t == 0) s_cnt = 0;
    if (b == 0) {
        if (t < 12) g_acc[t] = 0.0f;
        if (t == 12) g_done = 0;
    }
    for (int i = t; i < PLANE; i += 64) pos_map[i] = 0x7FFFFFFF;
    for (int i = t; i < MAXT * NA; i += 64) { lastBest[i] = -1; lastIgn[i] = -1; }
    __syncthreads();

    int ts = tsizes[b];
    if (ts > MAXT) ts = MAXT;

    const float AW[5] = {1.f, 2.f, 4.f, 2.f, 4.f};
    const float AH[5] = {1.f, 2.f, 4.f, 4.f, 2.f};

    if (t < ts) {
        const float* row = target + ((long)(b * MAXT + t)) * (13 + NCLS);
        float gx = row[0] * (1.0f / 16.0f);
        float gy = row[1] * (1.0f / 16.0f);
        float gh = row[3] * (1.0f / 16.0f);
        float gw = row[4] * (1.0f / 16.0f);
        int gi = (int)gx;
        int gj = (int)gy;
        int pos = gj * NW + gi;

        atomicMin(&pos_map[pos], t);

        int lbl = 0; float bv = row[13];
        #pragma unroll
        for (int c = 1; c < NCLS; c++) {
            float v = row[13 + c];
            if (v > bv) { bv = v; lbl = c; }
        }

        float garea = (gw + 1.0f) * (gh + 1.0f);
        float best_iou = -1.0f; int best = 0; unsigned ign = 0u;
        #pragma unroll
        for (int a = 0; a < 5; a++) {
            float iw = fmaxf(fminf(gw, AW[a]) + 1.0f, 0.0f);
            float ih = fmaxf(fminf(gh, AH[a]) + 1.0f, 0.0f);
            float inter = iw * ih;
            float aa = (AW[a] + 1.0f) * (AH[a] + 1.0f);
            float iou = inter / (garea + aa - inter + 1e-16f);
            if (iou > 0.5f) ign |= (1u << a);
            if (iou > best_iou) { best_iou = iou; best = a; }  // first-max tie
        }

        s_gi[t] = gi; s_gj[t] = gj; s_lbl[t] = lbl;
        s_tx[t] = gx - (float)gi;
        s_ty[t] = gy - (float)gj;
        s_tw[t] = logf(gw / AW[best] + 1e-16f);
        s_th[t] = logf(gh / AH[best] + 1e-16f);
        s_cor[t] = (int)ign | (best << 8) | (pos << 16);

        // prediction at best cell (for nCorrect)
        long base = ((((long)b * NA + best) * NH + gj) * NW + gi) * CH;
        float pc = pred[base + 0];
        float x = pred[base + 1], y = pred[base + 2];
        float h = pred[base + 3], w = pred[base + 4];
        float px = x + (float)gi, py = y + (float)gj;
        float pw = expf(w) * AW[best];
        float ph = expf(h) * AH[best];

        float gx1 = gx - gw * 0.5f, gx2 = gx + gw * 0.5f;
        float gy1 = gy - gh * 0.5f, gy2 = gy + gh * 0.5f;
        float px1 = px - pw * 0.5f, px2 = px + pw * 0.5f;
        float py1 = py - ph * 0.5f, py2 = py + ph * 0.5f;
        float iw2 = fmaxf(fminf(gx2, px2) - fmaxf(gx1, px1) + 1.0f, 0.0f);
        float ih2 = fmaxf(fminf(gy2, py2) - fmaxf(gy1, py1) + 1.0f, 0.0f);
        float inter2 = iw2 * ih2;
        float ga = (gx2 - gx1 + 1.0f) * (gy2 - gy1 + 1.0f);
        float pa = (px2 - px1 + 1.0f) * (py2 - py1 + 1.0f);
        float iou2 = inter2 / (ga + pa - inter2 + 1e-16f);

        int cb = 0; float cbv = pred[base + 5];
        #pragma unroll
        for (int c = 1; c < NCLS; c++) {
            float v = pred[base + 5 + c];
            if (v > cbv) { cbv = v; cb = c; }
        }
        int correct = (iou2 > 0.5f && cb == lbl && pc > 0.5f) ? 1 : 0;
        s_cor[t] |= (correct << 30);
    }
    __syncthreads();

    // LWW events against resolved slots
    if (t < ts) {
        int pk   = s_cor[t];
        int pos  = (pk >> 16) & 0x3FFF;
        int best = (pk >> 8) & 0x1F;
        unsigned ign = (unsigned)(pk & 0xFF);
        int slot = pos_map[pos];
        atomicMax(&lastBest[slot * NA + best], t);
        #pragma unroll
        for (int a = 0; a < 5; a++)
            if ((ign >> a) & 1u) atomicMax(&lastIgn[slot * NA + a], t);
    }
    __syncthreads();

    // Emit corrections: m = (lastBest>=0); owner = lastBest; cm = (lastBest >= lastIgn)
    if (t < ts) {
        int pos = s_gj[t] * NW + s_gi[t];
        if (pos_map[pos] == t) {
            #pragma unroll
            for (int a = 0; a < 5; a++) {
                int lb = lastBest[t * NA + a];
                int li = lastIgn[t * NA + a];
                if (lb >= 0) {
                    int cm = (lb >= li) ? 1 : 0;
                    int idx = atomicAdd(&s_cnt, 1);
                    int gidx = b * MAXE + idx;
                    g_ecell[gidx] = b * (NA * PLANE) + a * PLANE + pos;
                    g_einfo[gidx] = 1 | (cm << 1) | (s_lbl[lb] << 2);
                    g_etx[gidx] = s_tx[lb]; g_ety[gidx] = s_ty[lb];
                    g_etw[gidx] = s_tw[lb]; g_eth[gidx] = s_th[lb];
                } else if (li >= 0) {
                    int idx = atomicAdd(&s_cnt, 1);
                    int gidx = b * MAXE + idx;
                    g_ecell[gidx] = b * (NA * PLANE) + a * PLANE + pos;
                    g_einfo[gidx] = 0;
                }
            }
        }
    }
    __syncthreads();

    if (t == 0) {
        g_ecnt[b] = s_cnt;
        int nC = 0;
        for (int i = 0; i < ts; i++) nC += (s_cor[i] >> 30) & 1;
        g_nGT[b] = (float)ts;
        g_nC[b]  = (float)nC;
    }
}

__global__ void __launch_bounds__(MAIN_THREADS) k_main(const float* __restrict__ pred,
                                                       float* __restrict__ out) {
    __shared__ float red[MAIN_THREADS / 32][10];
    const int lane = threadIdx.x & 31;
    const int warp = threadIdx.x >> 5;

    if (blockIdx.x >= CORR_BLOCKS) {
        // ---- coalesced stream over the whole tensor; extract conf via mod-45 carry ----
        const float4* __restrict__ p4 = (const float4*)pred;
        const int base = (blockIdx.x - CORR_BLOCKS) * (MAIN_THREADS * F4_PER_THREAD) + threadIdx.x;
        // float index of first load, remainder mod 45
        int r = (int)(((long)base * 4) % 45);
        float neg = 0.0f, np = 0.0f;
        #pragma unroll 5
        for (int k = 0; k < F4_PER_THREAD; k++) {
            float4 v = __ldg(p4 + base + k * MAIN_THREADS);
            // conf present iff r in {0,42,43,44}
            bool hit = (r == 0) | (r >= 42);
            if (hit) {
                float c = (r == 0)  ? v.x :
                          (r == 44) ? v.y :
                          (r == 43) ? v.z : v.w;
                neg += fmaxf(c, 0.0f) + log1pf(expf(-fabsf(c)));
                np  += (c > 0.0f) ? 1.0f : 0.0f;
            }
            r += 34;                    // (4 * 256) mod 45
            if (r >= 45) r -= 45;
        }
        #pragma unroll
        for (int off = 16; off > 0; off >>= 1) {
            neg += __shfl_down_sync(0xFFFFFFFFu, neg, off);
            np  += __shfl_down_sync(0xFFFFFFFFu, np, off);
        }
        if (lane == 0) { red[warp][0] = neg; red[warp][1] = np; }
        __syncthreads();
        if (threadIdx.x == 0) {
            float sn = 0.0f, sp = 0.0f;
            #pragma unroll
            for (int w = 0; w < MAIN_THREADS / 32; w++) { sn += red[w][0]; sp += red[w][1]; }
            atomicAdd(&g_acc[4], sn);
            atomicAdd(&g_acc[9], sp);
        }
    } else {
        // ---- correction path: exact deltas vs default (m=0, cm=1) ----
        float acc[10];
        #pragma unroll
        for (int k = 0; k < 10; k++) acc[k] = 0.0f;

        const int tid = blockIdx.x * MAIN_THREADS + threadIdx.x;
        const int stride = CORR_BLOCKS * MAIN_THREADS;
        for (int b = 0; b < NB; b++) {
            int cnt = g_ecnt[b];
            for (int i = tid; i < cnt; i += stride) {
                int gidx = b * MAXE + i;
                int cell = g_ecell[gidx];
                int info = g_einfo[gidx];
                const float* p = pred + (size_t)cell * CH;
                float pc = p[0];
                float bce0 = fmaxf(pc, 0.0f) + log1pf(expf(-fabsf(pc)));
                if (info & 1) {             // masked cell
                    float bce1 = bce0 - pc;
                    if ((info >> 1) & 1) {  // cm=1: cmf 1 -> 0
                        acc[4] -= bce0; acc[5] -= 1.0f;
                    } else {                // cm=0,m=1: cmf stays 1, bce uses tconf=1
                        acc[4] += bce1 - bce0;
                    }
                    acc[6] += bce1;
                    acc[7] += 1.0f;
                    float dx = p[1] - g_etx[gidx]; acc[0] += dx * dx;
                    float dy = p[2] - g_ety[gidx]; acc[1] += dy * dy;
                    float dw = p[4] - g_etw[gidx]; acc[2] += dw * dw;
                    float dh = p[3] - g_eth[gidx]; acc[3] += dh * dh;
                    int lbl = info >> 2;
                    float mx = -FLT_MAX;
                    for (int c = 0; c < NCLS; c++) mx = fmaxf(mx, p[5 + c]);
                    float s = 0.0f;
                    for (int c = 0; c < NCLS; c++) s += expf(p[5 + c] - mx);
                    acc[8] += -(p[5 + lbl] - mx - logf(s));
                } else {                    // pure-ignore: cmf 1 -> 0
                    acc[4] -= bce0; acc[5] -= 1.0f;
                }
            }
        }

        #pragma unroll
        for (int k = 0; k < 10; k++) {
            float x = acc[k];
            #pragma unroll
            for (int off = 16; off > 0; off >>= 1)
                x += __shfl_down_sync(0xFFFFFFFFu, x, off);
            if (lane == 0) red[warp][k] = x;
        }
        __syncthreads();
        if (threadIdx.x == 0) {
            #pragma unroll
            for (int k = 0; k < 10; k++) {
                float x = 0.0f;
                #pragma unroll
                for (int w = 0; w < MAIN_THREADS / 32; w++) x += red[w][k];
                if (x != 0.0f) atomicAdd(&g_acc[k], x);
            }
        }
    }

    // ---- last-block-done finalization ----
    if (threadIdx.x == 0) {
        __threadfence();
        int old = atomicAdd(&g_done, 1);
        if (old == TOTAL_BLOCKS - 1) {
            volatile float* A = g_acc;
            float nM = A[7];
            float lx = A[0] / nM, ly = A[1] / nM, lw = A[2] / nM, lh = A[3] / nM;
            float neg_cnt = (float)NCELL + A[5];
            float lconf = A[4] / neg_cnt + A[6] / nM;
            float lcls = (1.0f / (float)NB) * A[8] / nM;
            float nGT = 0.0f, nC = 0.0f;
            for (int b = 0; b < NB; b++) { nGT += g_nGT[b]; nC += g_nC[b]; }
            float nP = A[9];
            out[0] = lx + ly + lw + lh + lconf + lcls;
            out[1] = lx + ly + lw + lh;
            out[2] = lconf;
            out[3] = lcls;
            out[4] = nC / fmaxf(nGT, 1.0f);
            out[5] = (nP > 0.0f) ? (nC / fmaxf(nP, 1.0f)) : 1.0f;
        }
    }
}

extern "C" void kernel_launch(void* const* d_in, const int* in_sizes, int n_in,
                              void* d_out, int out_size) {
    const float* pred   = (const float*)d_in[0];
    const float* target = (const float*)d_in[1];
    const int*   tsz    = (const int*)d_in[2];
    float* out = (float*)d_out;
    (void)in_sizes; (void)n_in; (void)out_size;

    k_build<<<NB, 64>>>(pred, target, tsz);
    k_main<<<TOTAL_BLOCKS, MAIN_THREADS>>>(pred, out);
}

// round 5
// speedup vs baseline: 3.5386x; 1.5025x over previous
#include <cuda_runtime.h>
#include <math.h>
#include <float.h>

#define NB 16
#define NA 5
#define NH 96
#define NW 96
#define MAXT 50
#define NCLS 40
#define CH (5 + NCLS)          // 45
#define NCELL (NB*NA*NH*NW)    // 737280
#define PLANE (NH*NW)          // 9216
#define MAXE 304

#define CORR_BLOCKS 8
#define MAIN_THREADS 256
#define U 16                                  // loads per thread (fully unrolled)
#define CONF_PER_WARP (4 * U)                 // 4 lines per warp-load
#define WARPS_PER_BLOCK (MAIN_THREADS / 32)
#define CONF_PER_BLOCK (CONF_PER_WARP * WARPS_PER_BLOCK)      // 512
#define STREAM_BLOCKS (NCELL / CONF_PER_BLOCK)                // 1440 exact
#define TOTAL_BLOCKS (CORR_BLOCKS + STREAM_BLOCKS)

// Compact correction list
__device__ int   g_ecnt[NB];
__device__ int   g_ecell[NB * MAXE];
__device__ int   g_einfo[NB * MAXE];   // bit0: m, bit1: cm, bits2+: label
__device__ float g_etx[NB * MAXE];
__device__ float g_ety[NB * MAXE];
__device__ float g_etw[NB * MAXE];
__device__ float g_eth[NB * MAXE];
__device__ float g_nGT[NB];
__device__ float g_nC[NB];
// acc: 0 sx,1 sy,2 sw,3 sh,4 neg_sum,5 neg_cnt_delta,6 pos_sum,7 nM,8 cls_sum,9 nProp
__device__ float g_acc[12];
__device__ int   g_done;

__global__ void __launch_bounds__(64) k_build(const float* __restrict__ pred,
                                              const float* __restrict__ target,
                                              const int*   __restrict__ tsizes) {
    const int b = blockIdx.x;
    const int t = threadIdx.x;

    __shared__ int   pos_map[PLANE];
    __shared__ int   lastBest[MAXT * NA];
    __shared__ int   lastIgn[MAXT * NA];
    __shared__ int   s_gi[MAXT], s_gj[MAXT], s_lbl[MAXT], s_cor[MAXT];
    __shared__ float s_tx[MAXT], s_ty[MAXT], s_tw[MAXT], s_th[MAXT];
    __shared__ int   s_cnt;

    if (t == 0) s_cnt = 0;
    if (b == 0) {
        if (t < 12) g_acc[t] = 0.0f;
        if (t == 12) g_done = 0;
    }
    for (int i = t; i < PLANE; i += 64) pos_map[i] = 0x7FFFFFFF;
    for (int i = t; i < MAXT * NA; i += 64) { lastBest[i] = -1; lastIgn[i] = -1; }
    __syncthreads();

    int ts = tsizes[b];
    if (ts > MAXT) ts = MAXT;

    const float AW[5] = {1.f, 2.f, 4.f, 2.f, 4.f};
    const float AH[5] = {1.f, 2.f, 4.f, 4.f, 2.f};

    if (t < ts) {
        const float* row = target + ((long)(b * MAXT + t)) * (13 + NCLS);
        float gx = row[0] * (1.0f / 16.0f);
        float gy = row[1] * (1.0f / 16.0f);
        float gh = row[3] * (1.0f / 16.0f);
        float gw = row[4] * (1.0f / 16.0f);
        int gi = (int)gx;
        int gj = (int)gy;
        int pos = gj * NW + gi;

        atomicMin(&pos_map[pos], t);

        int lbl = 0; float bv = row[13];
        #pragma unroll
        for (int c = 1; c < NCLS; c++) {
            float v = row[13 + c];
            if (v > bv) { bv = v; lbl = c; }
        }

        float garea = (gw + 1.0f) * (gh + 1.0f);
        float best_iou = -1.0f; int best = 0; unsigned ign = 0u;
        #pragma unroll
        for (int a = 0; a < 5; a++) {
            float iw = fmaxf(fminf(gw, AW[a]) + 1.0f, 0.0f);
            float ih = fmaxf(fminf(gh, AH[a]) + 1.0f, 0.0f);
            float inter = iw * ih;
            float aa = (AW[a] + 1.0f) * (AH[a] + 1.0f);
            float iou = inter / (garea + aa - inter + 1e-16f);
            if (iou > 0.5f) ign |= (1u << a);
            if (iou > best_iou) { best_iou = iou; best = a; }  // first-max tie
        }

        s_gi[t] = gi; s_gj[t] = gj; s_lbl[t] = lbl;
        s_tx[t] = gx - (float)gi;
        s_ty[t] = gy - (float)gj;
        s_tw[t] = logf(gw / AW[best] + 1e-16f);
        s_th[t] = logf(gh / AH[best] + 1e-16f);
        s_cor[t] = (int)ign | (best << 8) | (pos << 16);

        long base = ((((long)b * NA + best) * NH + gj) * NW + gi) * CH;
        float pc = pred[base + 0];
        float x = pred[base + 1], y = pred[base + 2];
        float h = pred[base + 3], w = pred[base + 4];
        float px = x + (float)gi, py = y + (float)gj;
        float pw = expf(w) * AW[best];
        float ph = expf(h) * AH[best];

        float gx1 = gx - gw * 0.5f, gx2 = gx + gw * 0.5f;
        float gy1 = gy - gh * 0.5f, gy2 = gy + gh * 0.5f;
        float px1 = px - pw * 0.5f, px2 = px + pw * 0.5f;
        float py1 = py - ph * 0.5f, py2 = py + ph * 0.5f;
        float iw2 = fmaxf(fminf(gx2, px2) - fmaxf(gx1, px1) + 1.0f, 0.0f);
        float ih2 = fmaxf(fminf(gy2, py2) - fmaxf(gy1, py1) + 1.0f, 0.0f);
        float inter2 = iw2 * ih2;
        float ga = (gx2 - gx1 + 1.0f) * (gy2 - gy1 + 1.0f);
        float pa = (px2 - px1 + 1.0f) * (py2 - py1 + 1.0f);
        float iou2 = inter2 / (ga + pa - inter2 + 1e-16f);

        int cb = 0; float cbv = pred[base + 5];
        #pragma unroll
        for (int c = 1; c < NCLS; c++) {
            float v = pred[base + 5 + c];
            if (v > cbv) { cbv = v; cb = c; }
        }
        int correct = (iou2 > 0.5f && cb == lbl && pc > 0.5f) ? 1 : 0;
        s_cor[t] |= (correct << 30);
    }
    __syncthreads();

    if (t < ts) {
        int pk   = s_cor[t];
        int pos  = (pk >> 16) & 0x3FFF;
        int best = (pk >> 8) & 0x1F;
        unsigned ign = (unsigned)(pk & 0xFF);
        int slot = pos_map[pos];
        atomicMax(&lastBest[slot * NA + best], t);
        #pragma unroll
        for (int a = 0; a < 5; a++)
            if ((ign >> a) & 1u) atomicMax(&lastIgn[slot * NA + a], t);
    }
    __syncthreads();

    if (t < ts) {
        int pos = s_gj[t] * NW + s_gi[t];
        if (pos_map[pos] == t) {
            #pragma unroll
            for (int a = 0; a < 5; a++) {
                int lb = lastBest[t * NA + a];
                int li = lastIgn[t * NA + a];
                if (lb >= 0) {
                    int cm = (lb >= li) ? 1 : 0;
                    int idx = atomicAdd(&s_cnt, 1);
                    int gidx = b * MAXE + idx;
                    g_ecell[gidx] = b * (NA * PLANE) + a * PLANE + pos;
                    g_einfo[gidx] = 1 | (cm << 1) | (s_lbl[lb] << 2);
                    g_etx[gidx] = s_tx[lb]; g_ety[gidx] = s_ty[lb];
                    g_etw[gidx] = s_tw[lb]; g_eth[gidx] = s_th[lb];
                } else if (li >= 0) {
                    int idx = atomicAdd(&s_cnt, 1);
                    int gidx = b * MAXE + idx;
                    g_ecell[gidx] = b * (NA * PLANE) + a * PLANE + pos;
                    g_einfo[gidx] = 0;
                }
            }
        }
    }
    __syncthreads();

    if (t == 0) {
        g_ecnt[b] = s_cnt;
        int nC = 0;
        for (int i = 0; i < ts; i++) nC += (s_cor[i] >> 30) & 1;
        g_nGT[b] = (float)ts;
        g_nC[b]  = (float)nC;
    }
}

__global__ void __launch_bounds__(MAIN_THREADS) k_main(const float* __restrict__ pred,
                                                       float* __restrict__ out) {
    __shared__ float red[WARPS_PER_BLOCK][10];
    const int lane = threadIdx.x & 31;
    const int warp = threadIdx.x >> 5;

    if (blockIdx.x >= CORR_BLOCKS) {
        // ---- line-exact conf gather: 8 lanes cooperatively load each conf's 128B line ----
        const float4* __restrict__ p4 = (const float4*)pred;
        const int o = lane & 7;                 // float4 slot within line
        const int s = lane >> 3;                // which of 4 lines this warp-load covers
        const int gw = (blockIdx.x - CORR_BLOCKS) * WARPS_PER_BLOCK + warp;
        const int c0 = gw * CONF_PER_WARP + s;  // conf index for k=0

        float4 v[U];
        #pragma unroll
        for (int k = 0; k < U; k++) {
            int c  = c0 + k * 4;
            int f  = 45 * c;                    // conf float index
            int f4 = ((f >> 5) << 3) + o;       // line base (in float4) + slot
            v[k] = __ldg(p4 + f4);
        }

        float neg = 0.0f, np = 0.0f;
        #pragma unroll
        for (int k = 0; k < U; k++) {
            int c = c0 + k * 4;
            int f = 45 * c;
            if (((f & 31) >> 2) == o) {         // this lane's float4 holds the conf
                int e = f & 3;
                float cv = (e == 0) ? v[k].x : (e == 1) ? v[k].y : (e == 2) ? v[k].z : v[k].w;
                neg += fmaxf(cv, 0.0f) + log1pf(expf(-fabsf(cv)));
                np  += (cv > 0.0f) ? 1.0f : 0.0f;
            }
        }

        #pragma unroll
        for (int off = 16; off > 0; off >>= 1) {
            neg += __shfl_down_sync(0xFFFFFFFFu, neg, off);
            np  += __shfl_down_sync(0xFFFFFFFFu, np, off);
        }
        if (lane == 0) { red[warp][0] = neg; red[warp][1] = np; }
        __syncthreads();
        if (threadIdx.x == 0) {
            float sn = 0.0f, sp = 0.0f;
            #pragma unroll
            for (int w = 0; w < WARPS_PER_BLOCK; w++) { sn += red[w][0]; sp += red[w][1]; }
            atomicAdd(&g_acc[4], sn);
            atomicAdd(&g_acc[9], sp);
        }
    } else {
        // ---- correction path: exact deltas vs default (m=0, cm=1) ----
        float acc[10];
        #pragma unroll
        for (int k = 0; k < 10; k++) acc[k] = 0.0f;

        const int tid = blockIdx.x * MAIN_THREADS + threadIdx.x;
        const int stride = CORR_BLOCKS * MAIN_THREADS;
        for (int b = 0; b < NB; b++) {
            int cnt = g_ecnt[b];
            for (int i = tid; i < cnt; i += stride) {
                int gidx = b * MAXE + i;
                int cell = g_ecell[gidx];
                int info = g_einfo[gidx];
                const float* p = pred + (size_t)cell * CH;
                float pc = p[0];
                float bce0 = fmaxf(pc, 0.0f) + log1pf(expf(-fabsf(pc)));
                if (info & 1) {
                    float bce1 = bce0 - pc;
                    if ((info >> 1) & 1) { acc[4] -= bce0; acc[5] -= 1.0f; }
                    else                 { acc[4] += bce1 - bce0; }
                    acc[6] += bce1;
                    acc[7] += 1.0f;
                    float dx = p[1] - g_etx[gidx]; acc[0] += dx * dx;
                    float dy = p[2] - g_ety[gidx]; acc[1] += dy * dy;
                    float dw = p[4] - g_etw[gidx]; acc[2] += dw * dw;
                    float dh = p[3] - g_eth[gidx]; acc[3] += dh * dh;
                    int lbl = info >> 2;
                    float mx = -FLT_MAX;
                    for (int c = 0; c < NCLS; c++) mx = fmaxf(mx, p[5 + c]);
                    float sxp = 0.0f;
                    for (int c = 0; c < NCLS; c++) sxp += expf(p[5 + c] - mx);
                    acc[8] += -(p[5 + lbl] - mx - logf(sxp));
                } else {
                    acc[4] -= bce0; acc[5] -= 1.0f;
                }
            }
        }

        #pragma unroll
        for (int k = 0; k < 10; k++) {
            float x = acc[k];
            #pragma unroll
            for (int off = 16; off > 0; off >>= 1)
                x += __shfl_down_sync(0xFFFFFFFFu, x, off);
            if (lane == 0) red[warp][k] = x;
        }
        __syncthreads();
        if (threadIdx.x == 0) {
            #pragma unroll
            for (int k = 0; k < 10; k++) {
                float x = 0.0f;
                #pragma unroll
                for (int w = 0; w < WARPS_PER_BLOCK; w++) x += red[w][k];
                if (x != 0.0f) atomicAdd(&g_acc[k], x);
            }
        }
    }

    // ---- last-block-done finalization ----
    if (threadIdx.x == 0) {
        __threadfence();
        int old = atomicAdd(&g_done, 1);
        if (old == TOTAL_BLOCKS - 1) {
            volatile float* A = g_acc;
            float nM = A[7];
            float lx = A[0] / nM, ly = A[1] / nM, lw = A[2] / nM, lh = A[3] / nM;
            float neg_cnt = (float)NCELL + A[5];
            float lconf = A[4] / neg_cnt + A[6] / nM;
            float lcls = (1.0f / (float)NB) * A[8] / nM;
            float nGT = 0.0f, nC = 0.0f;
            for (int b = 0; b < NB; b++) { nGT += g_nGT[b]; nC += g_nC[b]; }
            float nP = A[9];
            out[0] = lx + ly + lw + lh + lconf + lcls;
            out[1] = lx + ly + lw + lh;
            out[2] = lconf;
            out[3] = lcls;
            out[4] = nC / fmaxf(nGT, 1.0f);
            out[5] = (nP > 0.0f) ? (nC / fmaxf(nP, 1.0f)) : 1.0f;
        }
    }
}

extern "C" void kernel_launch(void* const* d_in, const int* in_sizes, int n_in,
                              void* d_out, int out_size) {
    const float* pred   = (const float*)d_in[0];
    const float* target = (const float*)d_in[1];
    const int*   tsz    = (const int*)d_in[2];
    float* out = (float*)d_out;
    (void)in_sizes; (void)n_in; (void)out_size;

    k_build<<<NB, 64>>>(pred, target, tsz);
    k_main<<<TOTAL_BLOCKS, MAIN_THREADS>>>(pred, out);
}